// round 14
// baseline (speedup 1.0000x reference)
#include <cuda_runtime.h>
#include <math_constants.h>

#define NF 300
#define WPB 8
#define FULL 0xffffffffu
#define GRID_BLOCKS 912   // 152 SMs * 6 CTAs/SM (GB300): exactly one wave

// ---------- slow-path machinery (full warp, one row), proven in R8 ----------
template <bool FIRST>
__device__ __forceinline__ void do_window_slow(const float* __restrict__ x,
                                               const float* __restrict__ k,
                                               int base, int lane,
                                               float& carry,
                                               float& b0o, float& b1o,
                                               unsigned& wout, int& pidxo)
{
    const int j0 = base + 2 * lane;
    const int j1 = j0 + 1;

    float2 own = make_float2(0.f, 0.f);
    if (FIRST || j0 < NF) own = __ldg(reinterpret_cast<const float2*>(x + j0));

    float2 lx = make_float2(0.f, 0.f);
    if (!FIRST && lane < 2)
        lx = __ldg(reinterpret_cast<const float2*>(x + base - 4 + 2 * lane));

    float2 rx = make_float2(0.f, 0.f);
    if (lane < 2 && base + 64 + 2 * lane < NF)
        rx = __ldg(reinterpret_cast<const float2*>(x + base + 64 + 2 * lane));

    const float bl2 = __shfl_sync(FULL, lx.x, 1);
    const float bl1 = __shfl_sync(FULL, lx.y, 1);
    const float bl3 = __shfl_sync(FULL, lx.y, 0);
    const float e64 = __shfl_sync(FULL, rx.x, 0);
    const float e65 = __shfl_sync(FULL, rx.y, 0);
    const float e66 = __shfl_sync(FULL, rx.x, 1);
    const float e67 = __shfl_sync(FULL, rx.y, 1);

    float xm3 = __shfl_up_sync(FULL, own.y, 2);
    float xm2 = __shfl_up_sync(FULL, own.x, 1);
    float xm1 = __shfl_up_sync(FULL, own.y, 1);
    if (lane == 0) { xm3 = bl3; xm2 = bl2; xm1 = bl1; }
    if (lane == 1) { xm3 = bl1; }
    float xp2 = __shfl_down_sync(FULL, own.x, 1);
    float xp3 = __shfl_down_sync(FULL, own.y, 1);
    float xp4 = __shfl_down_sync(FULL, own.x, 2);
    if (lane == 31) { xp2 = e64; xp3 = e65; xp4 = e66; }
    if (lane == 30) { xp4 = e64; }

    float b0 = xm3 * k[0];
    b0 = fmaf(xm2, k[1], b0); b0 = fmaf(xm1, k[2], b0); b0 = fmaf(own.x, k[3], b0);
    b0 = fmaf(own.y, k[4], b0); b0 = fmaf(xp2, k[5], b0); b0 = fmaf(xp3, k[6], b0);
    float b1 = xm2 * k[0];
    b1 = fmaf(xm1, k[1], b1); b1 = fmaf(own.x, k[2], b1); b1 = fmaf(own.y, k[3], b1);
    b1 = fmaf(xp2, k[4], b1); b1 = fmaf(xp3, k[5], b1); b1 = fmaf(xp4, k[6], b1);
    float b64 = xm1 * k[0];
    b64 = fmaf(own.x, k[1], b64); b64 = fmaf(own.y, k[2], b64); b64 = fmaf(e64, k[3], b64);
    b64 = fmaf(e65, k[4], b64); b64 = fmaf(e66, k[5], b64); b64 = fmaf(e67, k[6], b64);

    float bprev = __shfl_up_sync(FULL, b1, 1);
    if (lane == 0) bprev = carry;
    float bnext = __shfl_down_sync(FULL, b0, 1);
    if (lane == 31) bnext = b64;
    carry = __shfl_sync(FULL, b1, 31);

    bool pk0, pk1;
    if (FIRST) {
        pk0 = b0 > fmaxf(bprev, b1);      // bprev = -inf encodes j=0 rule
        pk1 = b1 > fmaxf(b0, bnext);
    } else {
        pk0 = (j0 < NF) && (b0 > fmaxf(bprev, b1));
        float right1 = (j1 == NF - 1) ? -CUDART_INF_F : bnext;
        pk1 = (j1 < NF) && (b1 > fmaxf(b0, right1));
    }

    b0o = b0; b1o = b1;
    wout  = __ballot_sync(FULL, pk0 || pk1);
    pidxo = pk1 ? j1 : j0;
}

__device__ __forceinline__ void merge2(unsigned w, int pidx,
                                       int& count, int& p0, int& p1)
{
    if (count >= 2 || !w) return;            // warp-uniform
    int q0 = __shfl_sync(FULL, pidx, __ffs(w) - 1);
    unsigned w2 = w & (w - 1);
    if (count == 0) {
        p0 = q0;
        if (w2) { p1 = __shfl_sync(FULL, pidx, __ffs(w2) - 1); count = 2; }
        else count = 1;
    } else {
        p1 = q0; count = 2;
    }
}

// Full-warp recomputation of one row (rare). Returns the loss on all lanes.
__device__ __noinline__ float slow_full_row(const float* __restrict__ x,
                                            float4 kv,
                                            float* __restrict__ sblur,
                                            int lane)
{
    float kk[7] = {kv.x, kv.y, kv.z, kv.w, kv.z, kv.y, kv.x};
    const float s2 = 2.0f / 299.0f;
    int count = 0, p0 = 0, p1 = 0;
    float carry = -CUDART_INF_F;

    {   // window 0
        float b0, b1; unsigned w; int pidx;
        do_window_slow<true>(x, kk, 0, lane, carry, b0, b1, w, pidx);
        merge2(w, pidx, count, p0, p1);
        *reinterpret_cast<float2*>(&sblur[2 * lane]) = make_float2(b0, b1);
    }
    for (int t = 1; t < 5 && count < 2; ++t) {
        float b0, b1; unsigned w; int pidx;
        do_window_slow<false>(x, kk, 64 * t, lane, carry, b0, b1, w, pidx);
        merge2(w, pidx, count, p0, p1);
        const int jj = 64 * t + 2 * lane;
        if (jj < NF)
            *reinterpret_cast<float2*>(&sblur[jj]) = make_float2(b0, b1);
    }
    __syncwarp();

    const int end = (count >= 2) ? ((p0 + p1) >> 1) : (NF - 1);
    float sw = 0.f, sf = 0.f;
    for (int j = lane; j < end; j += 32) {
        float e = __expf(sblur[j]);
        sw += e;
        sf = fmaf(e, fmaf((float)j, s2, -1.f), sf);
    }
#pragma unroll
    for (int off = 16; off > 0; off >>= 1) {
        sw += __shfl_xor_sync(FULL, sw, off);
        sf += __shfl_xor_sync(FULL, sf, off);
    }
    return -__fdividef(sf, sw);
}

// ------------- main kernel: persistent, 4 rows per warp-iteration -------------
__global__ __launch_bounds__(WPB * 32, 6)
void peak_mover_loss_kernel(const float* __restrict__ fr,
                            const float* __restrict__ kern,
                            float* __restrict__ out,
                            int B)
{
    __shared__ float s_blur[WPB][NF + 4];

    const int warp = threadIdx.x >> 5;
    const int lane = threadIdx.x & 31;
    const int li   = lane & 7;           // position within 8-lane segment
    const int seg  = lane >> 3;          // segment 0..3 = row offset

    // symmetric taps: k[4]=k[2], k[5]=k[1], k[6]=k[0] (exact by construction)
    const float4 kv = __ldg(reinterpret_cast<const float4*>(kern));
    const float k0 = kv.x, k1 = kv.y, k2 = kv.z, k3 = kv.w;
    const float s2 = 2.0f / 299.0f;

    const int numGroups  = (B + 3) >> 2;                 // 4 rows per group
    const int totalWarps = gridDim.x * WPB;
    const int warpGlobal = blockIdx.x * WPB + warp;

    for (int g = warpGlobal; g < numGroups; g += totalWarps) {
        const int rowBase = g * 4;
        const int myrow = min(rowBase + seg, B - 1);     // clamp for safe loads
        const float* x = fr + (size_t)myrow * NF;

        // ---- loads: own 8 elements + (li==7) tail x[64..67] ----
        const int j0 = 8 * li;                           // 0..56
        const float4 o0 = __ldg(reinterpret_cast<const float4*>(x + j0));
        const float4 o1 = __ldg(reinterpret_cast<const float4*>(x + j0 + 4));
        float4 t4 = make_float4(0.f, 0.f, 0.f, 0.f);
        if (li == 7) t4 = __ldg(reinterpret_cast<const float4*>(x + 64));

        // ---- halos from neighbor lanes (cross-segment reads fixed up) ----
        float xm3 = __shfl_up_sync(FULL, o1.y, 1);       // x[j0-3]
        float xm2 = __shfl_up_sync(FULL, o1.z, 1);       // x[j0-2]
        float xm1 = __shfl_up_sync(FULL, o1.w, 1);       // x[j0-1]
        if (li == 0) { xm3 = 0.f; xm2 = 0.f; xm1 = 0.f; } // SAME zero pad
        float xp1 = __shfl_down_sync(FULL, o0.x, 1);     // x[j0+8]
        float xp2 = __shfl_down_sync(FULL, o0.y, 1);     // x[j0+9]
        float xp3 = __shfl_down_sync(FULL, o0.z, 1);     // x[j0+10]
        if (li == 7) { xp1 = t4.x; xp2 = t4.y; xp3 = t4.z; }

        // ---- 7-tap blur at j0..j0+7 (symmetric pairing) ----
        float v[14] = {xm3, xm2, xm1,
                       o0.x, o0.y, o0.z, o0.w, o1.x, o1.y, o1.z, o1.w,
                       xp1, xp2, xp3};
        float b[8];
#pragma unroll
        for (int d = 0; d < 8; ++d)
            b[d] = fmaf(k0, v[d] + v[d + 6],
                   fmaf(k1, v[d + 1] + v[d + 5],
                   fmaf(k2, v[d + 2] + v[d + 4], k3 * v[d + 3])));
        // blur[64] (meaningful on li==7): x[61..67] = o1.y,o1.z,o1.w,t4
        float b64 = fmaf(k0, o1.y + t4.w,
                    fmaf(k1, o1.z + t4.z,
                    fmaf(k2, o1.w + t4.y, k3 * t4.x)));

        float bprev = __shfl_up_sync(FULL, b[7], 1);     // blur[j0-1]
        if (li == 0) bprev = -CUDART_INF_F;              // j=0 boundary rule
        float bnext = __shfl_down_sync(FULL, b[0], 1);   // blur[j0+8]
        if (li == 7) bnext = b64;

        // ---- 8-bit peak mask (strict local maxima; j<=63 < 299) ----
        unsigned m = 0;
        m |= (b[0] > fmaxf(bprev, b[1])) ? 1u : 0u;
#pragma unroll
        for (int d = 1; d < 7; ++d)
            m |= (b[d] > fmaxf(b[d - 1], b[d + 1])) ? (1u << d) : 0u;
        m |= (b[7] > fmaxf(b[6], bnext)) ? 128u : 0u;

        // ---- warp-uniform per-segment "has 2 peaks" (ballots only) ----
        unsigned w  = __ballot_sync(FULL, m != 0);
        unsigned w2 = __ballot_sync(FULL, (m & (m - 1)) != 0);

        bool hot = true;
#pragma unroll
        for (int s = 0; s < 4; ++s) {
            if (rowBase + s < B) {
                unsigned ws  = (w  >> (8 * s)) & 0xFFu;
                unsigned w2s = (w2 >> (8 * s)) & 0xFFu;
                if (!(((ws & (ws - 1)) != 0) || (ws & w2s))) hot = false;
            }
        }

        if (hot) {
            // ============ hot path: all rows resolved in window 0 ============
            const unsigned ws = (w >> (8 * seg)) & 0xFFu;
            const int L0 = __ffs(ws) - 1;
            const unsigned wsr = ws & (ws - 1);
            const int L1 = __ffs(wsr) - 1;
            unsigned m0 = __shfl_sync(FULL, m, (seg << 3) + (L0 & 7));
            unsigned m1 = __shfl_sync(FULL, m, (seg << 3) + (L1 & 7));
            int p0 = 8 * L0 + __ffs(m0) - 1;
            unsigned m0r = m0 & (m0 - 1);
            int p1 = m0r ? (8 * L0 + __ffs(m0r) - 1) : (8 * L1 + __ffs(m1) - 1);
            const int end = (p0 + p1) >> 1;               // 1..62, non-empty

            // softargmax: sum e, sum e*j = j0*sum(e) + sum(e*d)
            float sw = 0.f, sd = 0.f;
#pragma unroll
            for (int d = 0; d < 8; ++d) {
                if (j0 + d < end) {
                    float e = __expf(b[d]);
                    sw += e;
                    sd = fmaf(e, (float)d, sd);
                }
            }
            float sfj = fmaf((float)j0, sw, sd);
            // segment-local butterfly (8-lane segments: offsets 4,2,1)
#pragma unroll
            for (int off = 4; off > 0; off >>= 1) {
                sw  += __shfl_xor_sync(FULL, sw, off);
                sfj += __shfl_xor_sync(FULL, sfj, off);
            }
            // loss = -(softargmax) = 1 - s2 * sfj / sw
            if (li == 0 && rowBase + seg < B)
                out[myrow] = fmaf(-s2, __fdividef(sfj, sw), 1.0f);
        } else {
            // ============ rare slow path: full-warp per row ============
#pragma unroll
            for (int s = 0; s < 4; ++s) {
                const int rw = rowBase + s;
                if (rw < B) {
                    float loss = slow_full_row(fr + (size_t)rw * NF, kv,
                                               s_blur[warp], lane);
                    if (lane == 0) out[rw] = loss;
                }
            }
        }
    }
}

extern "C" void kernel_launch(void* const* d_in, const int* in_sizes, int n_in,
                              void* d_out, int out_size)
{
    const float* fr   = (const float*)d_in[0];
    const float* kern = (const float*)d_in[2];
    float* out = (float*)d_out;

    const int B = out_size;
    const int numGroups = (B + 3) / 4;
    const int maxBlocks = (numGroups + WPB - 1) / WPB;
    const int blocks = maxBlocks < GRID_BLOCKS ? maxBlocks : GRID_BLOCKS;
    peak_mover_loss_kernel<<<blocks, WPB * 32>>>(fr, kern, out, B);
}

// round 15
// speedup vs baseline: 1.1866x; 1.1866x over previous
#include <cuda_runtime.h>
#include <math_constants.h>

#define NF 300
#define WPB 8
#define FULL 0xffffffffu

// ---------- slow-path machinery (full warp, one row), proven in R8 ----------
template <bool FIRST>
__device__ __forceinline__ void do_window_slow(const float* __restrict__ x,
                                               const float* __restrict__ k,
                                               int base, int lane,
                                               float& carry,
                                               float& b0o, float& b1o,
                                               unsigned& wout, int& pidxo)
{
    const int j0 = base + 2 * lane;
    const int j1 = j0 + 1;

    float2 own = make_float2(0.f, 0.f);
    if (FIRST || j0 < NF) own = __ldg(reinterpret_cast<const float2*>(x + j0));

    float2 lx = make_float2(0.f, 0.f);
    if (!FIRST && lane < 2)
        lx = __ldg(reinterpret_cast<const float2*>(x + base - 4 + 2 * lane));

    float2 rx = make_float2(0.f, 0.f);
    if (lane < 2 && base + 64 + 2 * lane < NF)
        rx = __ldg(reinterpret_cast<const float2*>(x + base + 64 + 2 * lane));

    const float bl2 = __shfl_sync(FULL, lx.x, 1);
    const float bl1 = __shfl_sync(FULL, lx.y, 1);
    const float bl3 = __shfl_sync(FULL, lx.y, 0);
    const float e64 = __shfl_sync(FULL, rx.x, 0);
    const float e65 = __shfl_sync(FULL, rx.y, 0);
    const float e66 = __shfl_sync(FULL, rx.x, 1);
    const float e67 = __shfl_sync(FULL, rx.y, 1);

    float xm3 = __shfl_up_sync(FULL, own.y, 2);
    float xm2 = __shfl_up_sync(FULL, own.x, 1);
    float xm1 = __shfl_up_sync(FULL, own.y, 1);
    if (lane == 0) { xm3 = bl3; xm2 = bl2; xm1 = bl1; }
    if (lane == 1) { xm3 = bl1; }
    float xp2 = __shfl_down_sync(FULL, own.x, 1);
    float xp3 = __shfl_down_sync(FULL, own.y, 1);
    float xp4 = __shfl_down_sync(FULL, own.x, 2);
    if (lane == 31) { xp2 = e64; xp3 = e65; xp4 = e66; }
    if (lane == 30) { xp4 = e64; }

    float b0 = xm3 * k[0];
    b0 = fmaf(xm2, k[1], b0); b0 = fmaf(xm1, k[2], b0); b0 = fmaf(own.x, k[3], b0);
    b0 = fmaf(own.y, k[4], b0); b0 = fmaf(xp2, k[5], b0); b0 = fmaf(xp3, k[6], b0);
    float b1 = xm2 * k[0];
    b1 = fmaf(xm1, k[1], b1); b1 = fmaf(own.x, k[2], b1); b1 = fmaf(own.y, k[3], b1);
    b1 = fmaf(xp2, k[4], b1); b1 = fmaf(xp3, k[5], b1); b1 = fmaf(xp4, k[6], b1);
    float b64 = xm1 * k[0];
    b64 = fmaf(own.x, k[1], b64); b64 = fmaf(own.y, k[2], b64); b64 = fmaf(e64, k[3], b64);
    b64 = fmaf(e65, k[4], b64); b64 = fmaf(e66, k[5], b64); b64 = fmaf(e67, k[6], b64);

    float bprev = __shfl_up_sync(FULL, b1, 1);
    if (lane == 0) bprev = carry;
    float bnext = __shfl_down_sync(FULL, b0, 1);
    if (lane == 31) bnext = b64;
    carry = __shfl_sync(FULL, b1, 31);

    bool pk0, pk1;
    if (FIRST) {
        pk0 = b0 > fmaxf(bprev, b1);      // bprev = -inf encodes j=0 rule
        pk1 = b1 > fmaxf(b0, bnext);
    } else {
        pk0 = (j0 < NF) && (b0 > fmaxf(bprev, b1));
        float right1 = (j1 == NF - 1) ? -CUDART_INF_F : bnext;
        pk1 = (j1 < NF) && (b1 > fmaxf(b0, right1));
    }

    b0o = b0; b1o = b1;
    wout  = __ballot_sync(FULL, pk0 || pk1);
    pidxo = pk1 ? j1 : j0;
}

__device__ __forceinline__ void merge2(unsigned w, int pidx,
                                       int& count, int& p0, int& p1)
{
    if (count >= 2 || !w) return;            // warp-uniform
    int q0 = __shfl_sync(FULL, pidx, __ffs(w) - 1);
    unsigned w2 = w & (w - 1);
    if (count == 0) {
        p0 = q0;
        if (w2) { p1 = __shfl_sync(FULL, pidx, __ffs(w2) - 1); count = 2; }
        else count = 1;
    } else {
        p1 = q0; count = 2;
    }
}

// Full-warp recomputation of one row (rare). Returns the loss on all lanes.
__device__ __noinline__ float slow_full_row(const float* __restrict__ x,
                                            float4 kv,
                                            float* __restrict__ sblur,
                                            int lane)
{
    float kk[7] = {kv.x, kv.y, kv.z, kv.w, kv.z, kv.y, kv.x};
    const float s2 = 2.0f / 299.0f;
    int count = 0, p0 = 0, p1 = 0;
    float carry = -CUDART_INF_F;

    {   // window 0
        float b0, b1; unsigned w; int pidx;
        do_window_slow<true>(x, kk, 0, lane, carry, b0, b1, w, pidx);
        merge2(w, pidx, count, p0, p1);
        *reinterpret_cast<float2*>(&sblur[2 * lane]) = make_float2(b0, b1);
    }
    for (int t = 1; t < 5 && count < 2; ++t) {
        float b0, b1; unsigned w; int pidx;
        do_window_slow<false>(x, kk, 64 * t, lane, carry, b0, b1, w, pidx);
        merge2(w, pidx, count, p0, p1);
        const int jj = 64 * t + 2 * lane;
        if (jj < NF)
            *reinterpret_cast<float2*>(&sblur[jj]) = make_float2(b0, b1);
    }
    __syncwarp();

    const int end = (count >= 2) ? ((p0 + p1) >> 1) : (NF - 1);
    float sw = 0.f, sf = 0.f;
    for (int j = lane; j < end; j += 32) {
        float e = __expf(sblur[j]);
        sw += e;
        sf = fmaf(e, fmaf((float)j, s2, -1.f), sf);
    }
#pragma unroll
    for (int off = 16; off > 0; off >>= 1) {
        sw += __shfl_xor_sync(FULL, sw, off);
        sf += __shfl_xor_sync(FULL, sf, off);
    }
    return -__fdividef(sf, sw);
}

// ---------------------- main kernel: 4 rows per warp ----------------------
__global__ __launch_bounds__(WPB * 32, 6)
void peak_mover_loss_kernel(const float* __restrict__ fr,
                            const float* __restrict__ kern,
                            float* __restrict__ out,
                            int B)
{
    __shared__ float s_blur[WPB][NF + 4];

    const int warp = threadIdx.x >> 5;
    const int lane = threadIdx.x & 31;
    const int li   = lane & 7;           // position within 8-lane segment
    const int seg  = lane >> 3;          // segment 0..3 = row offset
    const int rowBase = (blockIdx.x * WPB + warp) * 4;
    if (rowBase >= B) return;
    const int myrow = min(rowBase + seg, B - 1);   // clamp for safe loads

    // symmetric taps: k[4]=k[2], k[5]=k[1], k[6]=k[0] (exact by construction)
    const float4 kv = __ldg(reinterpret_cast<const float4*>(kern));
    const float k0 = kv.x, k1 = kv.y, k2 = kv.z, k3 = kv.w;

    const float* x = fr + (size_t)myrow * NF;
    const float s2 = 2.0f / 299.0f;

    // ---- loads: own 8 elements + (li==7) tail x[64..67] ----
    const int j0 = 8 * li;                               // 0..56
    const float4 o0 = __ldg(reinterpret_cast<const float4*>(x + j0));
    const float4 o1 = __ldg(reinterpret_cast<const float4*>(x + j0 + 4));
    float4 t4 = make_float4(0.f, 0.f, 0.f, 0.f);
    if (li == 7) t4 = __ldg(reinterpret_cast<const float4*>(x + 64));

    // ---- halos from neighbor lanes (cross-segment reads fixed up) ----
    float xm3 = __shfl_up_sync(FULL, o1.y, 1);           // x[j0-3]
    float xm2 = __shfl_up_sync(FULL, o1.z, 1);           // x[j0-2]
    float xm1 = __shfl_up_sync(FULL, o1.w, 1);           // x[j0-1]
    if (li == 0) { xm3 = 0.f; xm2 = 0.f; xm1 = 0.f; }    // SAME zero pad
    float xp1 = __shfl_down_sync(FULL, o0.x, 1);         // x[j0+8]
    float xp2 = __shfl_down_sync(FULL, o0.y, 1);         // x[j0+9]
    float xp3 = __shfl_down_sync(FULL, o0.z, 1);         // x[j0+10]
    if (li == 7) { xp1 = t4.x; xp2 = t4.y; xp3 = t4.z; }

    // ---- 7-tap blur at j0..j0+7 (symmetric pairing) ----
    float v[14] = {xm3, xm2, xm1,
                   o0.x, o0.y, o0.z, o0.w, o1.x, o1.y, o1.z, o1.w,
                   xp1, xp2, xp3};
    float b[8];
#pragma unroll
    for (int d = 0; d < 8; ++d)
        b[d] = fmaf(k0, v[d] + v[d + 6],
               fmaf(k1, v[d + 1] + v[d + 5],
               fmaf(k2, v[d + 2] + v[d + 4], k3 * v[d + 3])));
    // blur[64] (meaningful on li==7): x[61..67] = o1.y,o1.z,o1.w,t4
    float b64 = fmaf(k0, o1.y + t4.w,
                fmaf(k1, o1.z + t4.z,
                fmaf(k2, o1.w + t4.y, k3 * t4.x)));

    float bprev = __shfl_up_sync(FULL, b[7], 1);         // blur[j0-1]
    if (li == 0) bprev = -CUDART_INF_F;                  // j=0 boundary rule
    float bnext = __shfl_down_sync(FULL, b[0], 1);       // blur[j0+8]
    if (li == 7) bnext = b64;

    // ---- 8-bit peak mask (strict local maxima; j<=63 < 299) ----
    unsigned m = 0;
    m |= (b[0] > fmaxf(bprev, b[1])) ? 1u : 0u;
#pragma unroll
    for (int d = 1; d < 7; ++d)
        m |= (b[d] > fmaxf(b[d - 1], b[d + 1])) ? (1u << d) : 0u;
    m |= (b[7] > fmaxf(b[6], bnext)) ? 128u : 0u;

    // ---- warp-uniform per-segment "has 2 peaks" (ballots only) ----
    unsigned w  = __ballot_sync(FULL, m != 0);
    unsigned w2 = __ballot_sync(FULL, (m & (m - 1)) != 0);

    // unresolved-rows bitmask (bit s set => row rowBase+s needs the slow path)
    unsigned unres = 0;
#pragma unroll
    for (int s = 0; s < 4; ++s) {
        if (rowBase + s < B) {
            unsigned ws  = (w  >> (8 * s)) & 0xFFu;
            unsigned w2s = (w2 >> (8 * s)) & 0xFFu;
            if (!(((ws & (ws - 1)) != 0) || (ws & w2s))) unres |= (1u << s);
        }
    }

    // ---- hot softmax for EVERY segment (unresolved results are discarded) ----
    {
        const unsigned ws = (w >> (8 * seg)) & 0xFFu;
        const int L0 = __ffs(ws) - 1;
        const unsigned wsr = ws & (ws - 1);
        const int L1 = __ffs(wsr) - 1;
        unsigned m0 = __shfl_sync(FULL, m, (seg << 3) + (L0 & 7));
        unsigned m1 = __shfl_sync(FULL, m, (seg << 3) + (L1 & 7));
        int p0 = 8 * L0 + __ffs(m0) - 1;
        unsigned m0r = m0 & (m0 - 1);
        int p1 = m0r ? (8 * L0 + __ffs(m0r) - 1) : (8 * L1 + __ffs(m1) - 1);
        const int end = (p0 + p1) >> 1;       // valid iff segment resolved

        // softargmax: sum e, sum e*j = j0*sum(e) + sum(e*d)
        float sw = 0.f, sd = 0.f;
#pragma unroll
        for (int d = 0; d < 8; ++d) {
            if (j0 + d < end) {
                float e = __expf(b[d]);
                sw += e;
                sd = fmaf(e, (float)d, sd);
            }
        }
        float sfj = fmaf((float)j0, sw, sd);
        // segment-local butterfly (8-lane segments: offsets 4,2,1)
#pragma unroll
        for (int off = 4; off > 0; off >>= 1) {
            sw  += __shfl_xor_sync(FULL, sw, off);
            sfj += __shfl_xor_sync(FULL, sfj, off);
        }
        // write only resolved, in-range segments
        const bool resolved = ((unres >> seg) & 1u) == 0u;
        if (li == 0 && resolved && rowBase + seg < B)
            out[myrow] = fmaf(-s2, __fdividef(sfj, sw), 1.0f);
    }

    // ---- rare slow path: ONLY the unresolved rows (warp-uniform mask) ----
    if (unres) {
#pragma unroll
        for (int s = 0; s < 4; ++s) {
            if ((unres >> s) & 1u) {
                const int rw = rowBase + s;
                float loss = slow_full_row(fr + (size_t)rw * NF, kv,
                                           s_blur[warp], lane);
                if (lane == 0) out[rw] = loss;
            }
        }
    }
}

extern "C" void kernel_launch(void* const* d_in, const int* in_sizes, int n_in,
                              void* d_out, int out_size)
{
    const float* fr   = (const float*)d_in[0];
    const float* kern = (const float*)d_in[2];
    float* out = (float*)d_out;

    const int B = out_size;
    const int rows_per_block = WPB * 4;
    const int blocks = (B + rows_per_block - 1) / rows_per_block;
    peak_mover_loss_kernel<<<blocks, WPB * 32>>>(fr, kern, out, B);
}

// round 16
// speedup vs baseline: 1.2259x; 1.0331x over previous
#include <cuda_runtime.h>
#include <math_constants.h>

#define NF 300
#define WPB 4
#define FULL 0xffffffffu

// ---------- slow-path machinery (full warp, one row), proven in R8 ----------
template <bool FIRST>
__device__ __forceinline__ void do_window_slow(const float* __restrict__ x,
                                               const float* __restrict__ k,
                                               int base, int lane,
                                               float& carry,
                                               float& b0o, float& b1o,
                                               unsigned& wout, int& pidxo)
{
    const int j0 = base + 2 * lane;
    const int j1 = j0 + 1;

    float2 own = make_float2(0.f, 0.f);
    if (FIRST || j0 < NF) own = __ldg(reinterpret_cast<const float2*>(x + j0));

    float2 lx = make_float2(0.f, 0.f);
    if (!FIRST && lane < 2)
        lx = __ldg(reinterpret_cast<const float2*>(x + base - 4 + 2 * lane));

    float2 rx = make_float2(0.f, 0.f);
    if (lane < 2 && base + 64 + 2 * lane < NF)
        rx = __ldg(reinterpret_cast<const float2*>(x + base + 64 + 2 * lane));

    const float bl2 = __shfl_sync(FULL, lx.x, 1);
    const float bl1 = __shfl_sync(FULL, lx.y, 1);
    const float bl3 = __shfl_sync(FULL, lx.y, 0);
    const float e64 = __shfl_sync(FULL, rx.x, 0);
    const float e65 = __shfl_sync(FULL, rx.y, 0);
    const float e66 = __shfl_sync(FULL, rx.x, 1);
    const float e67 = __shfl_sync(FULL, rx.y, 1);

    float xm3 = __shfl_up_sync(FULL, own.y, 2);
    float xm2 = __shfl_up_sync(FULL, own.x, 1);
    float xm1 = __shfl_up_sync(FULL, own.y, 1);
    if (lane == 0) { xm3 = bl3; xm2 = bl2; xm1 = bl1; }
    if (lane == 1) { xm3 = bl1; }
    float xp2 = __shfl_down_sync(FULL, own.x, 1);
    float xp3 = __shfl_down_sync(FULL, own.y, 1);
    float xp4 = __shfl_down_sync(FULL, own.x, 2);
    if (lane == 31) { xp2 = e64; xp3 = e65; xp4 = e66; }
    if (lane == 30) { xp4 = e64; }

    float b0 = xm3 * k[0];
    b0 = fmaf(xm2, k[1], b0); b0 = fmaf(xm1, k[2], b0); b0 = fmaf(own.x, k[3], b0);
    b0 = fmaf(own.y, k[4], b0); b0 = fmaf(xp2, k[5], b0); b0 = fmaf(xp3, k[6], b0);
    float b1 = xm2 * k[0];
    b1 = fmaf(xm1, k[1], b1); b1 = fmaf(own.x, k[2], b1); b1 = fmaf(own.y, k[3], b1);
    b1 = fmaf(xp2, k[4], b1); b1 = fmaf(xp3, k[5], b1); b1 = fmaf(xp4, k[6], b1);
    float b64 = xm1 * k[0];
    b64 = fmaf(own.x, k[1], b64); b64 = fmaf(own.y, k[2], b64); b64 = fmaf(e64, k[3], b64);
    b64 = fmaf(e65, k[4], b64); b64 = fmaf(e66, k[5], b64); b64 = fmaf(e67, k[6], b64);

    float bprev = __shfl_up_sync(FULL, b1, 1);
    if (lane == 0) bprev = carry;
    float bnext = __shfl_down_sync(FULL, b0, 1);
    if (lane == 31) bnext = b64;
    carry = __shfl_sync(FULL, b1, 31);

    bool pk0, pk1;
    if (FIRST) {
        pk0 = b0 > fmaxf(bprev, b1);      // bprev = -inf encodes j=0 rule
        pk1 = b1 > fmaxf(b0, bnext);
    } else {
        pk0 = (j0 < NF) && (b0 > fmaxf(bprev, b1));
        float right1 = (j1 == NF - 1) ? -CUDART_INF_F : bnext;
        pk1 = (j1 < NF) && (b1 > fmaxf(b0, right1));
    }

    b0o = b0; b1o = b1;
    wout  = __ballot_sync(FULL, pk0 || pk1);
    pidxo = pk1 ? j1 : j0;
}

__device__ __forceinline__ void merge2(unsigned w, int pidx,
                                       int& count, int& p0, int& p1)
{
    if (count >= 2 || !w) return;            // warp-uniform
    int q0 = __shfl_sync(FULL, pidx, __ffs(w) - 1);
    unsigned w2 = w & (w - 1);
    if (count == 0) {
        p0 = q0;
        if (w2) { p1 = __shfl_sync(FULL, pidx, __ffs(w2) - 1); count = 2; }
        else count = 1;
    } else {
        p1 = q0; count = 2;
    }
}

// Full-warp recomputation of one row (rare). Returns the loss on all lanes.
__device__ __noinline__ float slow_full_row(const float* __restrict__ x,
                                            float4 kv,
                                            float* __restrict__ sblur,
                                            int lane)
{
    float kk[7] = {kv.x, kv.y, kv.z, kv.w, kv.z, kv.y, kv.x};
    const float s2 = 2.0f / 299.0f;
    int count = 0, p0 = 0, p1 = 0;
    float carry = -CUDART_INF_F;

    {   // window 0
        float b0, b1; unsigned w; int pidx;
        do_window_slow<true>(x, kk, 0, lane, carry, b0, b1, w, pidx);
        merge2(w, pidx, count, p0, p1);
        *reinterpret_cast<float2*>(&sblur[2 * lane]) = make_float2(b0, b1);
    }
    for (int t = 1; t < 5 && count < 2; ++t) {
        float b0, b1; unsigned w; int pidx;
        do_window_slow<false>(x, kk, 64 * t, lane, carry, b0, b1, w, pidx);
        merge2(w, pidx, count, p0, p1);
        const int jj = 64 * t + 2 * lane;
        if (jj < NF)
            *reinterpret_cast<float2*>(&sblur[jj]) = make_float2(b0, b1);
    }
    __syncwarp();

    const int end = (count >= 2) ? ((p0 + p1) >> 1) : (NF - 1);
    float sw = 0.f, sf = 0.f;
    for (int j = lane; j < end; j += 32) {
        float e = __expf(sblur[j]);
        sw += e;
        sf = fmaf(e, fmaf((float)j, s2, -1.f), sf);
    }
#pragma unroll
    for (int off = 16; off > 0; off >>= 1) {
        sw += __shfl_xor_sync(FULL, sw, off);
        sf += __shfl_xor_sync(FULL, sf, off);
    }
    return -__fdividef(sf, sw);
}

// ---------------------- main kernel: 8 rows per warp ----------------------
__global__ __launch_bounds__(WPB * 32, 5)
void peak_mover_loss_kernel(const float* __restrict__ fr,
                            const float* __restrict__ kern,
                            float* __restrict__ out,
                            int B)
{
    __shared__ float s_blur[WPB][NF + 4];

    const int warp = threadIdx.x >> 5;
    const int lane = threadIdx.x & 31;
    const int li   = lane & 3;           // position within 4-lane segment
    const int seg  = lane >> 2;          // segment 0..7 = row offset
    const int rowBase = (blockIdx.x * WPB + warp) * 8;
    if (rowBase >= B) return;
    const int myrow = min(rowBase + seg, B - 1);   // clamp for safe loads

    // symmetric taps: k[4]=k[2], k[5]=k[1], k[6]=k[0] (exact by construction)
    const float4 kv = __ldg(reinterpret_cast<const float4*>(kern));
    const float k0 = kv.x, k1 = kv.y, k2 = kv.z, k3 = kv.w;

    const float* x = fr + (size_t)myrow * NF;
    const float s2 = 2.0f / 299.0f;

    // ---- loads: own 16 elements + (li==3) tail x[64..67] ----
    const int j0 = 16 * li;                              // 0, 16, 32, 48
    const float4 o0 = __ldg(reinterpret_cast<const float4*>(x + j0));
    const float4 o1 = __ldg(reinterpret_cast<const float4*>(x + j0 + 4));
    const float4 o2 = __ldg(reinterpret_cast<const float4*>(x + j0 + 8));
    const float4 o3 = __ldg(reinterpret_cast<const float4*>(x + j0 + 12));
    float4 t4 = make_float4(0.f, 0.f, 0.f, 0.f);
    if (li == 3) t4 = __ldg(reinterpret_cast<const float4*>(x + 64));

    // ---- halos from neighbor lanes (cross-segment reads fixed up) ----
    float xm3 = __shfl_up_sync(FULL, o3.y, 1);           // x[j0-3]
    float xm2 = __shfl_up_sync(FULL, o3.z, 1);           // x[j0-2]
    float xm1 = __shfl_up_sync(FULL, o3.w, 1);           // x[j0-1]
    if (li == 0) { xm3 = 0.f; xm2 = 0.f; xm1 = 0.f; }    // SAME zero pad
    float xp1 = __shfl_down_sync(FULL, o0.x, 1);         // x[j0+16]
    float xp2 = __shfl_down_sync(FULL, o0.y, 1);         // x[j0+17]
    float xp3 = __shfl_down_sync(FULL, o0.z, 1);         // x[j0+18]
    if (li == 3) { xp1 = t4.x; xp2 = t4.y; xp3 = t4.z; }

    // ---- 7-tap blur at j0..j0+15 (symmetric pairing) ----
    float v[22] = {xm3, xm2, xm1,
                   o0.x, o0.y, o0.z, o0.w,
                   o1.x, o1.y, o1.z, o1.w,
                   o2.x, o2.y, o2.z, o2.w,
                   o3.x, o3.y, o3.z, o3.w,
                   xp1, xp2, xp3};
    float b[16];
#pragma unroll
    for (int d = 0; d < 16; ++d)
        b[d] = fmaf(k0, v[d] + v[d + 6],
               fmaf(k1, v[d + 1] + v[d + 5],
               fmaf(k2, v[d + 2] + v[d + 4], k3 * v[d + 3])));
    // blur[64] (meaningful on li==3): x[61..67] = o3.y,o3.z,o3.w,t4
    float b64 = fmaf(k0, o3.y + t4.w,
                fmaf(k1, o3.z + t4.z,
                fmaf(k2, o3.w + t4.y, k3 * t4.x)));

    float bprev = __shfl_up_sync(FULL, b[15], 1);        // blur[j0-1]
    if (li == 0) bprev = -CUDART_INF_F;                  // j=0 boundary rule
    float bnext = __shfl_down_sync(FULL, b[0], 1);       // blur[j0+16]
    if (li == 3) bnext = b64;

    // ---- 16-bit peak mask (strict local maxima; j<=63 < 299) ----
    unsigned m = 0;
    m |= (b[0] > fmaxf(bprev, b[1])) ? 1u : 0u;
#pragma unroll
    for (int d = 1; d < 15; ++d)
        m |= (b[d] > fmaxf(b[d - 1], b[d + 1])) ? (1u << d) : 0u;
    m |= (b[15] > fmaxf(b[14], bnext)) ? (1u << 15) : 0u;

    // ---- warp-uniform per-segment "has 2 peaks" (ballots only) ----
    unsigned w  = __ballot_sync(FULL, m != 0);
    unsigned w2 = __ballot_sync(FULL, (m & (m - 1)) != 0);

    // unresolved-rows bitmask (bit s set => row rowBase+s needs slow path)
    unsigned unres = 0;
#pragma unroll
    for (int s = 0; s < 8; ++s) {
        if (rowBase + s < B) {
            unsigned ws  = (w  >> (4 * s)) & 0xFu;
            unsigned w2s = (w2 >> (4 * s)) & 0xFu;
            if (!(((ws & (ws - 1)) != 0) || (ws & w2s))) unres |= (1u << s);
        }
    }

    // ---- hot softmax for EVERY segment (unresolved results discarded) ----
    {
        const unsigned ws = (w >> (4 * seg)) & 0xFu;
        const int L0 = __ffs(ws) - 1;
        const unsigned wsr = ws & (ws - 1);
        const int L1 = __ffs(wsr) - 1;
        unsigned m0 = __shfl_sync(FULL, m, (seg << 2) + (L0 & 3));
        unsigned m1 = __shfl_sync(FULL, m, (seg << 2) + (L1 & 3));
        int p0 = 16 * L0 + __ffs(m0) - 1;
        unsigned m0r = m0 & (m0 - 1);
        int p1 = m0r ? (16 * L0 + __ffs(m0r) - 1) : (16 * L1 + __ffs(m1) - 1);
        const int end = (p0 + p1) >> 1;       // valid iff segment resolved

        // softargmax: sum e, sum e*j = j0*sum(e) + sum(e*d)
        float sw = 0.f, sd = 0.f;
#pragma unroll
        for (int d = 0; d < 16; ++d) {
            if (j0 + d < end) {
                float e = __expf(b[d]);
                sw += e;
                sd = fmaf(e, (float)d, sd);
            }
        }
        float sfj = fmaf((float)j0, sw, sd);
        // segment-local butterfly (4-lane segments: offsets 2,1)
#pragma unroll
        for (int off = 2; off > 0; off >>= 1) {
            sw  += __shfl_xor_sync(FULL, sw, off);
            sfj += __shfl_xor_sync(FULL, sfj, off);
        }
        // write only resolved, in-range segments
        const bool resolved = ((unres >> seg) & 1u) == 0u;
        if (li == 0 && resolved && rowBase + seg < B)
            out[myrow] = fmaf(-s2, __fdividef(sfj, sw), 1.0f);
    }

    // ---- rare slow path: ONLY the unresolved rows (warp-uniform mask) ----
    if (unres) {
#pragma unroll
        for (int s = 0; s < 8; ++s) {
            if ((unres >> s) & 1u) {
                const int rw = rowBase + s;
                float loss = slow_full_row(fr + (size_t)rw * NF, kv,
                                           s_blur[warp], lane);
                if (lane == 0) out[rw] = loss;
            }
        }
    }
}

extern "C" void kernel_launch(void* const* d_in, const int* in_sizes, int n_in,
                              void* d_out, int out_size)
{
    const float* fr   = (const float*)d_in[0];
    const float* kern = (const float*)d_in[2];
    float* out = (float*)d_out;

    const int B = out_size;
    const int rows_per_block = WPB * 8;
    const int blocks = (B + rows_per_block - 1) / rows_per_block;
    peak_mover_loss_kernel<<<blocks, WPB * 32>>>(fr, kern, out, B);
}